// round 2
// baseline (speedup 1.0000x reference)
#include <cuda_runtime.h>
#include <math.h>

// ---------------- problem constants ----------------
#define B_   4
#define N0_  8192
#define D_   1024
#define H_   16
#define DH_  64
#define CB   32      // block size C
#define W3   96      // 3*C window
#define LVLS 8

// pyramid token count: sum_{l=0..7} B*(N0>>l) = 4*16320
#define PYR_TOK 65280

// ---------------- device scratch (static, no allocation) ----------------
__device__ float g_q[(size_t)PYR_TOK * D_];
__device__ float g_k[(size_t)PYR_TOK * D_];
__device__ float g_v[(size_t)PYR_TOK * D_];
__device__ float g_num[(size_t)PYR_TOK * D_];
__device__ float g_den[(size_t)PYR_TOK * H_];
__device__ float g_m[PYR_TOK];
__device__ float g_att[(size_t)B_ * N0_ * D_];

// ---------------- SGEMM: C = (A[M,K] @ B[K,N]) * alpha + bias, optional row mask ----------------
// BM=BN=128, BK=8, 256 threads, 8x8 per-thread tile. M%128==0, N%128==0, K%8==0 assumed.
__global__ __launch_bounds__(256) void sgemm128(
    const float* __restrict__ A, const float* __restrict__ Bw, float* __restrict__ Co,
    int M, int N, int K, float alpha,
    const float* __restrict__ bias, const int* __restrict__ rowmask)
{
    __shared__ float As[8][128];
    __shared__ float Bs[8][128];
    const int tid = threadIdx.x;
    const int cRowBase = blockIdx.y * 128;
    const int cColBase = blockIdx.x * 128;

    const int aRow = tid >> 1;            // 0..127
    const int aCol = (tid & 1) * 4;       // 0 or 4
    const int bRow = tid >> 5;            // 0..7
    const int bCol = (tid & 31) * 4;      // 0..124
    const int tRow = (tid >> 4) * 8;      // 0..120
    const int tCol = (tid & 15) * 8;      // 0..120

    float acc[8][8];
    #pragma unroll
    for (int i = 0; i < 8; i++)
        #pragma unroll
        for (int j = 0; j < 8; j++) acc[i][j] = 0.f;

    const float* Aptr = A + (size_t)cRowBase * K;

    for (int k0 = 0; k0 < K; k0 += 8) {
        float4 a4 = *(const float4*)(Aptr + (size_t)aRow * K + k0 + aCol);
        As[aCol + 0][aRow] = a4.x;
        As[aCol + 1][aRow] = a4.y;
        As[aCol + 2][aRow] = a4.z;
        As[aCol + 3][aRow] = a4.w;
        float4 b4 = *(const float4*)(Bw + (size_t)(k0 + bRow) * N + cColBase + bCol);
        *(float4*)&Bs[bRow][bCol] = b4;
        __syncthreads();

        #pragma unroll
        for (int kk = 0; kk < 8; kk++) {
            float4 m0 = *(const float4*)&As[kk][tRow];
            float4 m1 = *(const float4*)&As[kk][tRow + 4];
            float4 n0 = *(const float4*)&Bs[kk][tCol];
            float4 n1 = *(const float4*)&Bs[kk][tCol + 4];
            float rm[8] = {m0.x, m0.y, m0.z, m0.w, m1.x, m1.y, m1.z, m1.w};
            float rn[8] = {n0.x, n0.y, n0.z, n0.w, n1.x, n1.y, n1.z, n1.w};
            #pragma unroll
            for (int i = 0; i < 8; i++)
                #pragma unroll
                for (int j = 0; j < 8; j++)
                    acc[i][j] += rm[i] * rn[j];
        }
        __syncthreads();
    }

    #pragma unroll
    for (int i = 0; i < 8; i++) {
        int row = cRowBase + tRow + i;
        float mk = rowmask ? (float)rowmask[row] : 1.f;
        #pragma unroll
        for (int j = 0; j < 8; j += 4) {
            int col = cColBase + tCol + j;
            float4 o;
            o.x = (acc[i][j + 0] * alpha + bias[col + 0]) * mk;
            o.y = (acc[i][j + 1] * alpha + bias[col + 1]) * mk;
            o.z = (acc[i][j + 2] * alpha + bias[col + 2]) * mk;
            o.w = (acc[i][j + 3] * alpha + bias[col + 3]) * mk;
            *(float4*)(Co + (size_t)row * N + col) = o;
        }
    }
}

// ---------------- mask init: g_m level 0 = (float)kmask ----------------
__global__ void mask_init(const int* __restrict__ kmask, float* __restrict__ m0, int n)
{
    int i = blockIdx.x * blockDim.x + threadIdx.x;
    if (i < n) m0[i] = (float)kmask[i];
}

// ---------------- coarsen: out[b,n2,c] = 0.5*(in[b,2n2,c] + in[b,2n2+1,c]) ----------------
__global__ void coarsen(const float* __restrict__ in, float* __restrict__ out, int nl2, int cols)
{
    int i = blockIdx.x * blockDim.x + threadIdx.x;
    int total = B_ * nl2 * cols;
    if (i >= total) return;
    int c  = i % cols;
    int n2 = (i / cols) % nl2;
    int b  = i / (cols * nl2);
    size_t a = ((size_t)b * (2 * nl2) + 2 * n2) * cols + c;
    out[i] = 0.5f * (in[a] + in[a + cols]);
}

// ---------------- hierarchical windowed attention at one level ----------------
// grid: (nb, H, B), 256 threads. Dynamic smem.
__global__ __launch_bounds__(256) void hier_attn(
    const float* __restrict__ qL, const float* __restrict__ kL, const float* __restrict__ vL,
    const float* __restrict__ mL, const float* __restrict__ rpbL,
    float* __restrict__ numL, float* __restrict__ denL, int nl, int lvl)
{
    extern __shared__ float sm[];
    float* sq   = sm;                       // 32 * 65
    float* sk   = sq + 32 * 65;             // 96 * 65
    float* sv   = sk + 96 * 65;             // 96 * 65
    float* sw   = sv + 96 * 65;             // 32 * 97
    float* srpb = sw + 32 * 97;             // 128
    float* smw  = srpb + 128;               // 96

    const int blk = blockIdx.x, h = blockIdx.y, b = blockIdx.z;
    const int tid = threadIdx.x;

    // q tile: 32 x 64
    const float* qbase = qL + ((size_t)b * nl + (size_t)blk * CB) * D_ + h * DH_;
    for (int i = tid; i < 32 * 16; i += 256) {
        int qi = i >> 4, d4 = (i & 15) * 4;
        float4 v4 = *(const float4*)(qbase + (size_t)qi * D_ + d4);
        sq[qi * 65 + d4 + 0] = v4.x; sq[qi * 65 + d4 + 1] = v4.y;
        sq[qi * 65 + d4 + 2] = v4.z; sq[qi * 65 + d4 + 3] = v4.w;
    }
    // k/v window: 96 x 64 (zero-padded outside [0, nl))
    for (int i = tid; i < 96 * 16; i += 256) {
        int p = i >> 4, d4 = (i & 15) * 4;
        int n = blk * CB + p - CB;
        float4 kv = make_float4(0.f, 0.f, 0.f, 0.f);
        float4 vv = make_float4(0.f, 0.f, 0.f, 0.f);
        if (n >= 0 && n < nl) {
            size_t off = ((size_t)b * nl + n) * D_ + h * DH_ + d4;
            kv = *(const float4*)(kL + off);
            vv = *(const float4*)(vL + off);
        }
        sk[p * 65 + d4 + 0] = kv.x; sk[p * 65 + d4 + 1] = kv.y;
        sk[p * 65 + d4 + 2] = kv.z; sk[p * 65 + d4 + 3] = kv.w;
        sv[p * 65 + d4 + 0] = vv.x; sv[p * 65 + d4 + 1] = vv.y;
        sv[p * 65 + d4 + 2] = vv.z; sv[p * 65 + d4 + 3] = vv.w;
    }
    for (int p = tid; p < 96; p += 256) {
        int n = blk * CB + p - CB;
        smw[p] = (n >= 0 && n < nl) ? mL[(size_t)b * nl + n] : 0.f;
    }
    for (int i = tid; i < 127; i += 256) srpb[i] = rpbL[h * 127 + i];
    __syncthreads();

    // logits + exp + masks -> sw[32][96]. Each thread: 1 qi x 4 p.
    for (int i = tid; i < 32 * 24; i += 256) {
        int qi = i / 24;
        int p0 = (i % 24) * 4;
        float acc0 = 0.f, acc1 = 0.f, acc2 = 0.f, acc3 = 0.f;
        const float* qr = &sq[qi * 65];
        #pragma unroll
        for (int d = 0; d < 64; d++) {
            float a = qr[d];
            acc0 += a * sk[(p0 + 0) * 65 + d];
            acc1 += a * sk[(p0 + 1) * 65 + d];
            acc2 += a * sk[(p0 + 2) * 65 + d];
            acc3 += a * sk[(p0 + 3) * 65 + d];
        }
        #pragma unroll
        for (int j = 0; j < 4; j++) {
            int p = p0 + j;
            float lg = (j == 0 ? acc0 : j == 1 ? acc1 : j == 2 ? acc2 : acc3);
            lg += srpb[p - qi + CB - 1];
            float valid = 1.f;
            if (lvl > 0) {
                int bk3 = p >> 5, pl = p & 31;
                bool inv = (bk3 == 1) ||
                           (bk3 == 0 && qi < 16 && pl >= 16) ||
                           (bk3 == 2 && qi >= 16 && pl < 16);
                valid = inv ? 0.f : 1.f;
            }
            sw[qi * 97 + p] = expf(lg) * valid * smw[p];
        }
    }
    __syncthreads();

    // den: row sums
    if (tid < 32) {
        float s = 0.f;
        #pragma unroll
        for (int p = 0; p < 96; p++) s += sw[tid * 97 + p];
        denL[((size_t)b * nl + blk * CB + tid) * H_ + h] = s;
    }

    // num = sw[32x96] @ sv[96x64]. Each thread: 1 qi x 4 d.
    for (int i = tid; i < 32 * 16; i += 256) {
        int qi = i >> 4;
        int d0 = (i & 15) * 4;
        float a0 = 0.f, a1 = 0.f, a2 = 0.f, a3 = 0.f;
        const float* wr = &sw[qi * 97];
        #pragma unroll
        for (int p = 0; p < 96; p++) {
            float w = wr[p];
            a0 += w * sv[p * 65 + d0 + 0];
            a1 += w * sv[p * 65 + d0 + 1];
            a2 += w * sv[p * 65 + d0 + 2];
            a3 += w * sv[p * 65 + d0 + 3];
        }
        float4 o = make_float4(a0, a1, a2, a3);
        *(float4*)(numL + ((size_t)b * nl + blk * CB + qi) * D_ + h * DH_ + d0) = o;
    }
}

// ---------------- combine: gather 8 levels, divide, qmask ----------------
__global__ void combine(const float* __restrict__ num, const float* __restrict__ den,
                        const int* __restrict__ qmask, float* __restrict__ att)
{
    int i = blockIdx.x * blockDim.x + threadIdx.x;
    if (i >= B_ * N0_ * D_) return;
    int dh = i & 63;
    int h  = (i >> 6) & 15;
    int n  = (i >> 10) & (N0_ - 1);
    int b  = i >> 23;  // N0_*D_ = 2^23
    float ns = 0.f, ds = 0.f;
    size_t toff = 0;
    #pragma unroll
    for (int l = 0; l < LVLS; l++) {
        int nl = N0_ >> l;
        size_t tk = toff + (size_t)b * nl + (n >> l);
        ns += num[tk * D_ + h * DH_ + dh];
        ds += den[tk * H_ + h];
        toff += (size_t)B_ * nl;
    }
    att[i] = ns / (ds + 1e-9f) * (float)qmask[b * N0_ + n];
}

// ---------------- host launch ----------------
extern "C" void kernel_launch(void* const* d_in, const int* in_sizes, int n_in,
                              void* d_out, int out_size)
{
    const float* inputs_q  = (const float*)d_in[0];
    const float* inputs_kv = (const float*)d_in[1];
    const int*   qmask     = (const int*)d_in[2];
    const int*   kmask     = (const int*)d_in[3];
    const float* Wq        = (const float*)d_in[4];
    const float* bq        = (const float*)d_in[5];
    const float* Wk        = (const float*)d_in[6];
    const float* bk        = (const float*)d_in[7];
    const float* Wv        = (const float*)d_in[8];
    const float* bv        = (const float*)d_in[9];
    const float* Wo        = (const float*)d_in[10];
    const float* bo        = (const float*)d_in[11];
    const float* rpb       = (const float*)d_in[12];
    float* out             = (float*)d_out;

    float *qp, *kp, *vp, *nump, *denp, *mp, *attp;
    cudaGetSymbolAddress((void**)&qp,   g_q);
    cudaGetSymbolAddress((void**)&kp,   g_k);
    cudaGetSymbolAddress((void**)&vp,   g_v);
    cudaGetSymbolAddress((void**)&nump, g_num);
    cudaGetSymbolAddress((void**)&denp, g_den);
    cudaGetSymbolAddress((void**)&mp,   g_m);
    cudaGetSymbolAddress((void**)&attp, g_att);

    const int ATTN_SMEM = (32 * 65 + 96 * 65 + 96 * 65 + 32 * 97 + 128 + 96) * 4;
    cudaFuncSetAttribute(hier_attn, cudaFuncAttributeMaxDynamicSharedMemorySize, ATTN_SMEM);

    const int M = B_ * N0_;     // 32768
    const float scale = 0.125f; // 1/sqrt(64)

    dim3 gemmGrid(D_ / 128, M / 128);
    sgemm128<<<gemmGrid, 256>>>(inputs_q, Wq, qp, M, D_, D_, scale, bq, nullptr);
    sgemm128<<<gemmGrid, 256>>>(inputs_kv, Wk, kp, M, D_, D_, 1.f, bk, nullptr);
    sgemm128<<<gemmGrid, 256>>>(inputs_kv, Wv, vp, M, D_, D_, 1.f, bv, kmask);

    mask_init<<<(B_ * N0_ + 255) / 256, 256>>>(kmask, mp, B_ * N0_);

    size_t toff = 0;
    int nl = N0_;
    for (int l = 0; l < LVLS; l++) {
        dim3 ag(nl / CB, H_, B_);
        hier_attn<<<ag, 256, ATTN_SMEM>>>(
            qp + toff * D_, kp + toff * D_, vp + toff * D_, mp + toff,
            rpb + (size_t)l * H_ * (4 * CB - 1),
            nump + toff * D_, denp + toff * H_, nl, l);
        if (l < LVLS - 1) {
            int nl2 = nl / 2;
            size_t toff2 = toff + (size_t)B_ * nl;
            int tot = B_ * nl2 * D_;
            coarsen<<<(tot + 255) / 256, 256>>>(qp + toff * D_, qp + toff2 * D_, nl2, D_);
            coarsen<<<(tot + 255) / 256, 256>>>(kp + toff * D_, kp + toff2 * D_, nl2, D_);
            coarsen<<<(tot + 255) / 256, 256>>>(vp + toff * D_, vp + toff2 * D_, nl2, D_);
            int totm = B_ * nl2;
            coarsen<<<(totm + 255) / 256, 256>>>(mp + toff, mp + toff2, nl2, 1);
        }
        toff += (size_t)B_ * nl;
        nl >>= 1;
    }

    int totc = B_ * N0_ * D_;
    combine<<<(totc + 255) / 256, 256>>>(nump, denp, qmask, attp);

    sgemm128<<<gemmGrid, 256>>>(attp, Wo, out, M, D_, D_, 1.f, bo, nullptr);
}

// round 4
// speedup vs baseline: 1.5426x; 1.5426x over previous
#include <cuda_runtime.h>
#include <math.h>
#include <stdint.h>

// ---------------- problem constants ----------------
#define B_   4
#define N0_  8192
#define D_   1024
#define H_   16
#define DH_  64
#define CB   32
#define LVLS 8
#define PYR_TOK 65280

// ---------------- device scratch ----------------
__device__ float g_q[(size_t)PYR_TOK * D_];
__device__ float g_k[(size_t)PYR_TOK * D_];
__device__ float g_v[(size_t)PYR_TOK * D_];
__device__ float g_num[(size_t)PYR_TOK * D_];
__device__ float g_den[(size_t)PYR_TOK * H_];
__device__ float g_m[PYR_TOK];
__device__ float g_att[(size_t)B_ * N0_ * D_];

__device__ __forceinline__ float cvt_tf32f(float f) {
    uint32_t r;
    asm("cvt.rna.tf32.f32 %0, %1;" : "=r"(r) : "f"(f));
    return __uint_as_float(r);
}

__device__ __forceinline__ void mma_tf32(float* c, const uint32_t* a, const uint32_t* b) {
    asm volatile(
        "mma.sync.aligned.m16n8k8.row.col.f32.tf32.tf32.f32 "
        "{%0,%1,%2,%3}, {%4,%5,%6,%7}, {%8,%9}, {%0,%1,%2,%3};"
        : "+f"(c[0]), "+f"(c[1]), "+f"(c[2]), "+f"(c[3])
        : "r"(a[0]), "r"(a[1]), "r"(a[2]), "r"(a[3]), "r"(b[0]), "r"(b[1]));
}

// ---------------- tf32 mma.sync GEMM ----------------
// C[M,N] = (A[M,K] @ Bw[K,N]) * alpha + bias, optional row mask.
// Tile 128x128, BK=32, 256 threads (8 warps, 2x4), warp tile 64x32.
// smem: As[2][128][36] (18KB ea), Bs[2][32][136] (17KB ea) -> 70KB total.
#define AS_STRIDE 36
#define BS_STRIDE 136
#define AS_FLOATS (128 * AS_STRIDE)
#define BS_FLOATS (32 * BS_STRIDE)
#define GEMM_SMEM ((2 * AS_FLOATS + 2 * BS_FLOATS) * 4)

__global__ __launch_bounds__(256) void gemm_tf32(
    const float* __restrict__ A, const float* __restrict__ Bw, float* __restrict__ Co,
    int M, int N, int K, float alpha,
    const float* __restrict__ bias, const int* __restrict__ rowmask)
{
    extern __shared__ float smf[];
    float* As0 = smf;
    float* As1 = smf + AS_FLOATS;
    float* Bs0 = smf + 2 * AS_FLOATS;
    float* Bs1 = smf + 2 * AS_FLOATS + BS_FLOATS;

    const int tid  = threadIdx.x;
    const int warp = tid >> 5;
    const int lane = tid & 31;
    const int wr   = warp >> 2;          // 0..1  (64-row slab)
    const int wc   = warp & 3;           // 0..3  (32-col slab)
    const int g    = lane >> 2;          // 0..7
    const int tig  = lane & 3;           // 0..3

    const int m0 = blockIdx.y * 128;
    const int n0 = blockIdx.x * 128;

    // global load indices (4 float4 each for A and B per iteration)
    const int aRow[1] = {0};
    float4 aStage[4], bStage[4];

    float acc[4][4][4];
    #pragma unroll
    for (int i = 0; i < 4; i++)
        #pragma unroll
        for (int j = 0; j < 4; j++)
            #pragma unroll
            for (int q = 0; q < 4; q++) acc[i][j][q] = 0.f;

    const int NIT = K / 32;

    // ---- helpers as lambdas ----
    auto load_regs = [&](int it) {
        const int k0 = it * 32;
        #pragma unroll
        for (int ch = 0; ch < 4; ch++) {
            int idx = tid + ch * 256;            // 0..1023
            int r = idx >> 3, kk = (idx & 7) * 4;
            aStage[ch] = *(const float4*)(A + (size_t)(m0 + r) * K + k0 + kk);
        }
        #pragma unroll
        for (int ch = 0; ch < 4; ch++) {
            int idx = tid + ch * 256;
            int kk = idx >> 5, c4 = (idx & 31) * 4;
            bStage[ch] = *(const float4*)(Bw + (size_t)(k0 + kk) * N + n0 + c4);
        }
    };
    auto store_smem = [&](float* Asd, float* Bsd) {
        #pragma unroll
        for (int ch = 0; ch < 4; ch++) {
            int idx = tid + ch * 256;
            int r = idx >> 3, kk = (idx & 7) * 4;
            float* p = Asd + r * AS_STRIDE + kk;
            p[0] = cvt_tf32f(aStage[ch].x); p[1] = cvt_tf32f(aStage[ch].y);
            p[2] = cvt_tf32f(aStage[ch].z); p[3] = cvt_tf32f(aStage[ch].w);
        }
        #pragma unroll
        for (int ch = 0; ch < 4; ch++) {
            int idx = tid + ch * 256;
            int kk = idx >> 5, c4 = (idx & 31) * 4;
            float* p = Bsd + kk * BS_STRIDE + c4;
            p[0] = cvt_tf32f(bStage[ch].x); p[1] = cvt_tf32f(bStage[ch].y);
            p[2] = cvt_tf32f(bStage[ch].z); p[3] = cvt_tf32f(bStage[ch].w);
        }
    };
    auto compute = [&](const float* Ass, const float* Bss) {
        #pragma unroll
        for (int ks = 0; ks < 4; ks++) {
            const int kb = ks * 8;
            uint32_t bf[4][2];
            #pragma unroll
            for (int nf = 0; nf < 4; nf++) {
                int col = wc * 32 + nf * 8 + g;
                bf[nf][0] = __float_as_uint(Bss[(kb + tig)     * BS_STRIDE + col]);
                bf[nf][1] = __float_as_uint(Bss[(kb + tig + 4) * BS_STRIDE + col]);
            }
            #pragma unroll
            for (int mf = 0; mf < 4; mf++) {
                int r = wr * 64 + mf * 16 + g;
                uint32_t af[4];
                af[0] = __float_as_uint(Ass[ r      * AS_STRIDE + kb + tig]);
                af[1] = __float_as_uint(Ass[(r + 8) * AS_STRIDE + kb + tig]);
                af[2] = __float_as_uint(Ass[ r      * AS_STRIDE + kb + tig + 4]);
                af[3] = __float_as_uint(Ass[(r + 8) * AS_STRIDE + kb + tig + 4]);
                #pragma unroll
                for (int nf = 0; nf < 4; nf++)
                    mma_tf32(acc[mf][nf], af, bf[nf]);
            }
        }
    };

    // prologue
    load_regs(0);
    store_smem(As0, Bs0);
    __syncthreads();

    for (int it = 0; it < NIT; ++it) {
        const int s = it & 1;
        if (it + 1 < NIT) load_regs(it + 1);
        compute(s ? As1 : As0, s ? Bs1 : Bs0);
        if (it + 1 < NIT) store_smem(s ? As0 : As1, s ? Bs0 : Bs1);
        __syncthreads();
    }

    // epilogue: acc[mf][nf] -> c0:(row g, col 2*tig), c1:(g, 2*tig+1), c2:(g+8, 2*tig), c3:(g+8, 2*tig+1)
    #pragma unroll
    for (int mf = 0; mf < 4; mf++) {
        int r0 = m0 + wr * 64 + mf * 16 + g;
        int r1 = r0 + 8;
        float mk0 = rowmask ? (float)rowmask[r0] : 1.f;
        float mk1 = rowmask ? (float)rowmask[r1] : 1.f;
        #pragma unroll
        for (int nf = 0; nf < 4; nf++) {
            int col = n0 + wc * 32 + nf * 8 + 2 * tig;
            float b0 = bias[col], b1 = bias[col + 1];
            float2 o0, o1;
            o0.x = (acc[mf][nf][0] * alpha + b0) * mk0;
            o0.y = (acc[mf][nf][1] * alpha + b1) * mk0;
            o1.x = (acc[mf][nf][2] * alpha + b0) * mk1;
            o1.y = (acc[mf][nf][3] * alpha + b1) * mk1;
            *(float2*)(Co + (size_t)r0 * N + col) = o0;
            *(float2*)(Co + (size_t)r1 * N + col) = o1;
        }
    }
    (void)aRow;
}

// ---------------- mask init ----------------
__global__ void mask_init(const int* __restrict__ kmask, float* __restrict__ m0, int n)
{
    int i = blockIdx.x * blockDim.x + threadIdx.x;
    if (i < n) m0[i] = (float)kmask[i];
}

// ---------------- coarsen ----------------
__global__ void coarsen(const float* __restrict__ in, float* __restrict__ out, int nl2, int cols)
{
    int i = blockIdx.x * blockDim.x + threadIdx.x;
    int total = B_ * nl2 * cols;
    if (i >= total) return;
    int c  = i % cols;
    int n2 = (i / cols) % nl2;
    int b  = i / (cols * nl2);
    size_t a = ((size_t)b * (2 * nl2) + 2 * n2) * cols + c;
    out[i] = 0.5f * (in[a] + in[a + cols]);
}

// ---------------- hierarchical windowed attention ----------------
__global__ __launch_bounds__(256) void hier_attn(
    const float* __restrict__ qL, const float* __restrict__ kL, const float* __restrict__ vL,
    const float* __restrict__ mL, const float* __restrict__ rpbL,
    float* __restrict__ numL, float* __restrict__ denL, int nl, int lvl)
{
    extern __shared__ float sm[];
    float* sq   = sm;                       // 32 * 65
    float* sk   = sq + 32 * 65;             // 96 * 65
    float* sv   = sk + 96 * 65;             // 96 * 65
    float* sw   = sv + 96 * 65;             // 32 * 97
    float* srpb = sw + 32 * 97;             // 128
    float* smw  = srpb + 128;               // 96

    const int blk = blockIdx.x, h = blockIdx.y, b = blockIdx.z;
    const int tid = threadIdx.x;

    const float* qbase = qL + ((size_t)b * nl + (size_t)blk * CB) * D_ + h * DH_;
    for (int i = tid; i < 32 * 16; i += 256) {
        int qi = i >> 4, d4 = (i & 15) * 4;
        float4 v4 = *(const float4*)(qbase + (size_t)qi * D_ + d4);
        sq[qi * 65 + d4 + 0] = v4.x; sq[qi * 65 + d4 + 1] = v4.y;
        sq[qi * 65 + d4 + 2] = v4.z; sq[qi * 65 + d4 + 3] = v4.w;
    }
    for (int i = tid; i < 96 * 16; i += 256) {
        int p = i >> 4, d4 = (i & 15) * 4;
        int n = blk * CB + p - CB;
        float4 kv = make_float4(0.f, 0.f, 0.f, 0.f);
        float4 vv = make_float4(0.f, 0.f, 0.f, 0.f);
        if (n >= 0 && n < nl) {
            size_t off = ((size_t)b * nl + n) * D_ + h * DH_ + d4;
            kv = *(const float4*)(kL + off);
            vv = *(const float4*)(vL + off);
        }
        sk[p * 65 + d4 + 0] = kv.x; sk[p * 65 + d4 + 1] = kv.y;
        sk[p * 65 + d4 + 2] = kv.z; sk[p * 65 + d4 + 3] = kv.w;
        sv[p * 65 + d4 + 0] = vv.x; sv[p * 65 + d4 + 1] = vv.y;
        sv[p * 65 + d4 + 2] = vv.z; sv[p * 65 + d4 + 3] = vv.w;
    }
    for (int p = tid; p < 96; p += 256) {
        int n = blk * CB + p - CB;
        smw[p] = (n >= 0 && n < nl) ? mL[(size_t)b * nl + n] : 0.f;
    }
    for (int i = tid; i < 127; i += 256) srpb[i] = rpbL[h * 127 + i];
    __syncthreads();

    for (int i = tid; i < 32 * 24; i += 256) {
        int qi = i / 24;
        int p0 = (i % 24) * 4;
        float acc0 = 0.f, acc1 = 0.f, acc2 = 0.f, acc3 = 0.f;
        const float* qr = &sq[qi * 65];
        #pragma unroll
        for (int d = 0; d < 64; d++) {
            float a = qr[d];
            acc0 += a * sk[(p0 + 0) * 65 + d];
            acc1 += a * sk[(p0 + 1) * 65 + d];
            acc2 += a * sk[(p0 + 2) * 65 + d];
            acc3 += a * sk[(p0 + 3) * 65 + d];
        }
        #pragma unroll
        for (int j = 0; j < 4; j++) {
            int p = p0 + j;
            float lg = (j == 0 ? acc0 : j == 1 ? acc1 : j == 2 ? acc2 : acc3);
            lg += srpb[p - qi + CB - 1];
            float valid = 1.f;
            if (lvl > 0) {
                int bk3 = p >> 5, pl = p & 31;
                bool inv = (bk3 == 1) ||
                           (bk3 == 0 && qi < 16 && pl >= 16) ||
                           (bk3 == 2 && qi >= 16 && pl < 16);
                valid = inv ? 0.f : 1.f;
            }
            sw[qi * 97 + p] = expf(lg) * valid * smw[p];
        }
    }
    __syncthreads();

    if (tid < 32) {
        float s = 0.f;
        #pragma unroll
        for (int p = 0; p < 96; p++) s += sw[tid * 97 + p];
        denL[((size_t)b * nl + blk * CB + tid) * H_ + h] = s;
    }

    for (int i = tid; i < 32 * 16; i += 256) {
        int qi = i >> 4;
        int d0 = (i & 15) * 4;
        float a0 = 0.f, a1 = 0.f, a2 = 0.f, a3 = 0.f;
        const float* wr = &sw[qi * 97];
        #pragma unroll
        for (int p = 0; p < 96; p++) {
            float w = wr[p];
            a0 += w * sv[p * 65 + d0 + 0];
            a1 += w * sv[p * 65 + d0 + 1];
            a2 += w * sv[p * 65 + d0 + 2];
            a3 += w * sv[p * 65 + d0 + 3];
        }
        float4 o = make_float4(a0, a1, a2, a3);
        *(float4*)(numL + ((size_t)b * nl + blk * CB + qi) * D_ + h * DH_ + d0) = o;
    }
}

// ---------------- combine ----------------
__global__ void combine(const float* __restrict__ num, const float* __restrict__ den,
                        const int* __restrict__ qmask, float* __restrict__ att)
{
    int i = blockIdx.x * blockDim.x + threadIdx.x;
    if (i >= B_ * N0_ * D_) return;
    int dh = i & 63;
    int h  = (i >> 6) & 15;
    int n  = (i >> 10) & (N0_ - 1);
    int b  = i >> 23;
    float ns = 0.f, ds = 0.f;
    size_t toff = 0;
    #pragma unroll
    for (int l = 0; l < LVLS; l++) {
        int nl = N0_ >> l;
        size_t tk = toff + (size_t)b * nl + (n >> l);
        ns += num[tk * D_ + h * DH_ + dh];
        ds += den[tk * H_ + h];
        toff += (size_t)B_ * nl;
    }
    att[i] = ns / (ds + 1e-9f) * (float)qmask[b * N0_ + n];
}

// ---------------- host launch ----------------
extern "C" void kernel_launch(void* const* d_in, const int* in_sizes, int n_in,
                              void* d_out, int out_size)
{
    const float* inputs_q  = (const float*)d_in[0];
    const float* inputs_kv = (const float*)d_in[1];
    const int*   qmask     = (const int*)d_in[2];
    const int*   kmask     = (const int*)d_in[3];
    const float* Wq        = (const float*)d_in[4];
    const float* bq        = (const float*)d_in[5];
    const float* Wk        = (const float*)d_in[6];
    const float* bk        = (const float*)d_in[7];
    const float* Wv        = (const float*)d_in[8];
    const float* bv        = (const float*)d_in[9];
    const float* Wo        = (const float*)d_in[10];
    const float* bo        = (const float*)d_in[11];
    const float* rpb       = (const float*)d_in[12];
    float* out             = (float*)d_out;

    float *qp, *kp, *vp, *nump, *denp, *mp, *attp;
    cudaGetSymbolAddress((void**)&qp,   g_q);
    cudaGetSymbolAddress((void**)&kp,   g_k);
    cudaGetSymbolAddress((void**)&vp,   g_v);
    cudaGetSymbolAddress((void**)&nump, g_num);
    cudaGetSymbolAddress((void**)&denp, g_den);
    cudaGetSymbolAddress((void**)&mp,   g_m);
    cudaGetSymbolAddress((void**)&attp, g_att);

    const int ATTN_SMEM = (32 * 65 + 96 * 65 + 96 * 65 + 32 * 97 + 128 + 96) * 4;
    cudaFuncSetAttribute(hier_attn, cudaFuncAttributeMaxDynamicSharedMemorySize, ATTN_SMEM);
    cudaFuncSetAttribute(gemm_tf32, cudaFuncAttributeMaxDynamicSharedMemorySize, GEMM_SMEM);

    const int M = B_ * N0_;
    const float scale = 0.125f;

    dim3 gemmGrid(D_ / 128, M / 128);
    gemm_tf32<<<gemmGrid, 256, GEMM_SMEM>>>(inputs_q,  Wq, qp, M, D_, D_, scale, bq, nullptr);
    gemm_tf32<<<gemmGrid, 256, GEMM_SMEM>>>(inputs_kv, Wk, kp, M, D_, D_, 1.f, bk, nullptr);
    gemm_tf32<<<gemmGrid, 256, GEMM_SMEM>>>(inputs_kv, Wv, vp, M, D_, D_, 1.f, bv, kmask);

    mask_init<<<(B_ * N0_ + 255) / 256, 256>>>(kmask, mp, B_ * N0_);

    size_t toff = 0;
    int nl = N0_;
    for (int l = 0; l < LVLS; l++) {
        dim3 ag(nl / CB, H_, B_);
        hier_attn<<<ag, 256, ATTN_SMEM>>>(
            qp + toff * D_, kp + toff * D_, vp + toff * D_, mp + toff,
            rpb + (size_t)l * H_ * (4 * CB - 1),
            nump + toff * D_, denp + toff * H_, nl, l);
        if (l < LVLS - 1) {
            int nl2 = nl / 2;
            size_t toff2 = toff + (size_t)B_ * nl;
            int tot = B_ * nl2 * D_;
            coarsen<<<(tot + 255) / 256, 256>>>(qp + toff * D_, qp + toff2 * D_, nl2, D_);
            coarsen<<<(tot + 255) / 256, 256>>>(kp + toff * D_, kp + toff2 * D_, nl2, D_);
            coarsen<<<(tot + 255) / 256, 256>>>(vp + toff * D_, vp + toff2 * D_, nl2, D_);
            int totm = B_ * nl2;
            coarsen<<<(totm + 255) / 256, 256>>>(mp + toff, mp + toff2, nl2, 1);
        }
        toff += (size_t)B_ * nl;
        nl >>= 1;
    }

    int totc = B_ * N0_ * D_;
    combine<<<(totc + 255) / 256, 256>>>(nump, denp, qmask, attp);

    gemm_tf32<<<gemmGrid, 256, GEMM_SMEM>>>(attp, Wo, out, M, D_, D_, 1.f, bo, nullptr);
}

// round 5
// speedup vs baseline: 2.8448x; 1.8442x over previous
#include <cuda_runtime.h>
#include <cuda_fp16.h>
#include <math.h>
#include <stdint.h>

// ---------------- problem constants ----------------
#define B_   4
#define N0_  8192
#define D_   1024
#define H_   16
#define DH_  64
#define CB   32
#define LVLS 8
#define PYR_TOK 65280

// ---------------- device scratch ----------------
__device__ float g_q[(size_t)PYR_TOK * D_];
__device__ float g_k[(size_t)PYR_TOK * D_];
__device__ float g_v[(size_t)PYR_TOK * D_];
__device__ float g_num[(size_t)PYR_TOK * D_];
__device__ float g_den[(size_t)PYR_TOK * H_];
__device__ float g_m[PYR_TOK];
__device__ float g_att[(size_t)B_ * N0_ * D_];

__device__ __forceinline__ uint32_t packh2(float lo, float hi) {
    __half2 h = __floats2half2_rn(lo, hi);
    return *reinterpret_cast<uint32_t*>(&h);
}

__device__ __forceinline__ void mma_f16(float* c, const uint32_t* a, const uint32_t* b) {
    asm volatile(
        "mma.sync.aligned.m16n8k16.row.col.f32.f16.f16.f32 "
        "{%0,%1,%2,%3}, {%4,%5,%6,%7}, {%8,%9}, {%0,%1,%2,%3};"
        : "+f"(c[0]), "+f"(c[1]), "+f"(c[2]), "+f"(c[3])
        : "r"(a[0]), "r"(a[1]), "r"(a[2]), "r"(a[3]), "r"(b[0]), "r"(b[1]));
}

// ---------------- fp16 mma.sync GEMM ----------------
// C[M,N] = (A@Bw)*alpha + bias, optional row mask.
// Tile 128x128, BK=32, 256 threads (8 warps 2x4), warp tile 64x32.
// smem words: As[128][20] (word = 2 k-consecutive fp16), Bs[16][136] (word = (k,k+1) pair at col n).
#define AS_WSTRIDE 20
#define BS_WSTRIDE 136
#define AS_WORDS (128 * AS_WSTRIDE)
#define BS_WORDS (16 * BS_WSTRIDE)
#define GEMM_SMEM ((2 * AS_WORDS + 2 * BS_WORDS) * 4)

__global__ __launch_bounds__(256) void gemm_f16(
    const float* __restrict__ A, const float* __restrict__ Bw, float* __restrict__ Co,
    int M, int N, int K, float alpha,
    const float* __restrict__ bias, const int* __restrict__ rowmask)
{
    extern __shared__ uint32_t smw[];
    uint32_t* As0 = smw;
    uint32_t* As1 = smw + AS_WORDS;
    uint32_t* Bs0 = smw + 2 * AS_WORDS;
    uint32_t* Bs1 = Bs0 + BS_WORDS;

    const int tid  = threadIdx.x;
    const int warp = tid >> 5;
    const int lane = tid & 31;
    const int wr   = warp >> 2;
    const int wc   = warp & 3;
    const int g    = lane >> 2;
    const int tig  = lane & 3;

    const int m0 = blockIdx.y * 128;
    const int n0 = blockIdx.x * 128;

    float4 aStage[4];
    float4 bStage0[2], bStage1[2];

    float acc[4][4][4];
    #pragma unroll
    for (int i = 0; i < 4; i++)
        #pragma unroll
        for (int j = 0; j < 4; j++)
            #pragma unroll
            for (int q = 0; q < 4; q++) acc[i][j][q] = 0.f;

    const int NIT = K / 32;

    auto load_regs = [&](int it) {
        const int k0 = it * 32;
        #pragma unroll
        for (int ch = 0; ch < 4; ch++) {
            int idx = tid + ch * 256;
            int r = idx >> 3, kk4 = (idx & 7) * 4;
            aStage[ch] = *(const float4*)(A + (size_t)(m0 + r) * K + k0 + kk4);
        }
        #pragma unroll
        for (int ch = 0; ch < 2; ch++) {
            int idx = tid + ch * 256;              // 0..511
            int kp = idx >> 5, n4 = (idx & 31) * 4;
            bStage0[ch] = *(const float4*)(Bw + (size_t)(k0 + 2 * kp)     * N + n0 + n4);
            bStage1[ch] = *(const float4*)(Bw + (size_t)(k0 + 2 * kp + 1) * N + n0 + n4);
        }
    };
    auto store_smem = [&](uint32_t* Asd, uint32_t* Bsd) {
        #pragma unroll
        for (int ch = 0; ch < 4; ch++) {
            int idx = tid + ch * 256;
            int r = idx >> 3, kk4 = (idx & 7) * 4;
            uint2 w;
            w.x = packh2(aStage[ch].x, aStage[ch].y);
            w.y = packh2(aStage[ch].z, aStage[ch].w);
            *(uint2*)(Asd + r * AS_WSTRIDE + kk4 / 2) = w;
        }
        #pragma unroll
        for (int ch = 0; ch < 2; ch++) {
            int idx = tid + ch * 256;
            int kp = idx >> 5, n4 = (idx & 31) * 4;
            uint4 u;
            u.x = packh2(bStage0[ch].x, bStage1[ch].x);
            u.y = packh2(bStage0[ch].y, bStage1[ch].y);
            u.z = packh2(bStage0[ch].z, bStage1[ch].z);
            u.w = packh2(bStage0[ch].w, bStage1[ch].w);
            *(uint4*)(Bsd + kp * BS_WSTRIDE + n4) = u;
        }
    };
    auto compute = [&](const uint32_t* Ass, const uint32_t* Bss) {
        #pragma unroll
        for (int ks = 0; ks < 2; ks++) {
            uint32_t bf[4][2];
            #pragma unroll
            for (int nf = 0; nf < 4; nf++) {
                int col = wc * 32 + nf * 8 + g;
                bf[nf][0] = Bss[(ks * 8 + tig)     * BS_WSTRIDE + col];
                bf[nf][1] = Bss[(ks * 8 + tig + 4) * BS_WSTRIDE + col];
            }
            #pragma unroll
            for (int mf = 0; mf < 4; mf++) {
                int row = wr * 64 + mf * 16 + g;
                uint32_t af[4];
                af[0] = Ass[ row      * AS_WSTRIDE + ks * 8 + tig];
                af[1] = Ass[(row + 8) * AS_WSTRIDE + ks * 8 + tig];
                af[2] = Ass[ row      * AS_WSTRIDE + ks * 8 + tig + 4];
                af[3] = Ass[(row + 8) * AS_WSTRIDE + ks * 8 + tig + 4];
                #pragma unroll
                for (int nf = 0; nf < 4; nf++)
                    mma_f16(acc[mf][nf], af, bf[nf]);
            }
        }
    };

    load_regs(0);
    store_smem(As0, Bs0);
    __syncthreads();

    for (int it = 0; it < NIT; ++it) {
        const int s = it & 1;
        if (it + 1 < NIT) load_regs(it + 1);
        compute(s ? As1 : As0, s ? Bs1 : Bs0);
        if (it + 1 < NIT) store_smem(s ? As0 : As1, s ? Bs0 : Bs1);
        __syncthreads();
    }

    #pragma unroll
    for (int mf = 0; mf < 4; mf++) {
        int r0 = m0 + wr * 64 + mf * 16 + g;
        int r1 = r0 + 8;
        float mk0 = rowmask ? (float)rowmask[r0] : 1.f;
        float mk1 = rowmask ? (float)rowmask[r1] : 1.f;
        #pragma unroll
        for (int nf = 0; nf < 4; nf++) {
            int col = n0 + wc * 32 + nf * 8 + 2 * tig;
            float b0 = bias[col], b1 = bias[col + 1];
            float2 o0, o1;
            o0.x = (acc[mf][nf][0] * alpha + b0) * mk0;
            o0.y = (acc[mf][nf][1] * alpha + b1) * mk0;
            o1.x = (acc[mf][nf][2] * alpha + b0) * mk1;
            o1.y = (acc[mf][nf][3] * alpha + b1) * mk1;
            *(float2*)(Co + (size_t)r0 * N + col) = o0;
            *(float2*)(Co + (size_t)r1 * N + col) = o1;
        }
    }
}

// ---------------- mask init ----------------
__global__ void mask_init(const int* __restrict__ kmask, float* __restrict__ m0, int n)
{
    int i = blockIdx.x * blockDim.x + threadIdx.x;
    if (i < n) m0[i] = (float)kmask[i];
}

// ---------------- coarsen ----------------
__global__ void coarsen(const float* __restrict__ in, float* __restrict__ out, int nl2, int cols)
{
    int i = blockIdx.x * blockDim.x + threadIdx.x;
    int total = B_ * nl2 * cols;
    if (i >= total) return;
    int c  = i % cols;
    int n2 = (i / cols) % nl2;
    int b  = i / (cols * nl2);
    size_t a = ((size_t)b * (2 * nl2) + 2 * n2) * cols + c;
    out[i] = 0.5f * (in[a] + in[a + cols]);
}

// ---------------- hierarchical windowed attention ----------------
// strides 68 for 16B-aligned float4 LDS
#define SQS 68
#define SKS 68
#define SVS 68
#define SWS 97
#define ATTN_SMEM ((32 * SQS + 96 * SKS + 96 * SVS + 32 * SWS + 128 + 96) * 4)

__global__ __launch_bounds__(256) void hier_attn(
    const float* __restrict__ qL, const float* __restrict__ kL, const float* __restrict__ vL,
    const float* __restrict__ mL, const float* __restrict__ rpbL,
    float* __restrict__ numL, float* __restrict__ denL, int nl, int lvl)
{
    extern __shared__ float sm[];
    float* sq   = sm;                        // 32 * 68
    float* sk   = sq + 32 * SQS;             // 96 * 68
    float* sv   = sk + 96 * SKS;             // 96 * 68
    float* sw   = sv + 96 * SVS;             // 32 * 97
    float* srpb = sw + 32 * SWS;             // 128
    float* smw  = srpb + 128;                // 96

    const int blk = blockIdx.x, h = blockIdx.y, b = blockIdx.z;
    const int tid = threadIdx.x;

    const float* qbase = qL + ((size_t)b * nl + (size_t)blk * CB) * D_ + h * DH_;
    for (int i = tid; i < 32 * 16; i += 256) {
        int qi = i >> 4, d4 = (i & 15) * 4;
        float4 v4 = *(const float4*)(qbase + (size_t)qi * D_ + d4);
        *(float4*)&sq[qi * SQS + d4] = v4;
    }
    for (int i = tid; i < 96 * 16; i += 256) {
        int p = i >> 4, d4 = (i & 15) * 4;
        int n = blk * CB + p - CB;
        float4 kv = make_float4(0.f, 0.f, 0.f, 0.f);
        float4 vv = make_float4(0.f, 0.f, 0.f, 0.f);
        if (n >= 0 && n < nl) {
            size_t off = ((size_t)b * nl + n) * D_ + h * DH_ + d4;
            kv = *(const float4*)(kL + off);
            vv = *(const float4*)(vL + off);
        }
        *(float4*)&sk[p * SKS + d4] = kv;
        *(float4*)&sv[p * SVS + d4] = vv;
    }
    for (int p = tid; p < 96; p += 256) {
        int n = blk * CB + p - CB;
        smw[p] = (n >= 0 && n < nl) ? mL[(size_t)b * nl + n] : 0.f;
    }
    for (int i = tid; i < 127; i += 256) srpb[i] = rpbL[h * 127 + i];
    __syncthreads();

    // logits: 192 tasks, each 4 qi x 4 p
    if (tid < 192) {
        int qi0 = (tid / 24) * 4;
        int p0  = (tid % 24) * 4;
        float acc[4][4];
        #pragma unroll
        for (int r = 0; r < 4; r++)
            #pragma unroll
            for (int j = 0; j < 4; j++) acc[r][j] = 0.f;
        #pragma unroll
        for (int d = 0; d < 64; d += 4) {
            float4 qv[4], kv[4];
            #pragma unroll
            for (int r = 0; r < 4; r++) qv[r] = *(const float4*)&sq[(qi0 + r) * SQS + d];
            #pragma unroll
            for (int j = 0; j < 4; j++) kv[j] = *(const float4*)&sk[(p0 + j) * SKS + d];
            #pragma unroll
            for (int r = 0; r < 4; r++)
                #pragma unroll
                for (int j = 0; j < 4; j++) {
                    acc[r][j] += qv[r].x * kv[j].x + qv[r].y * kv[j].y
                               + qv[r].z * kv[j].z + qv[r].w * kv[j].w;
                }
        }
        #pragma unroll
        for (int r = 0; r < 4; r++) {
            int qi = qi0 + r;
            #pragma unroll
            for (int j = 0; j < 4; j++) {
                int p = p0 + j;
                float lg = acc[r][j] + srpb[p - qi + CB - 1];
                float valid = 1.f;
                if (lvl > 0) {
                    int bk3 = p >> 5, pl = p & 31;
                    bool inv = (bk3 == 1) ||
                               (bk3 == 0 && qi < 16 && pl >= 16) ||
                               (bk3 == 2 && qi >= 16 && pl < 16);
                    valid = inv ? 0.f : 1.f;
                }
                sw[qi * SWS + p] = expf(lg) * valid * smw[p];
            }
        }
    }
    __syncthreads();

    if (tid < 32) {
        float s = 0.f;
        #pragma unroll
        for (int p = 0; p < 96; p++) s += sw[tid * SWS + p];
        denL[((size_t)b * nl + blk * CB + tid) * H_ + h] = s;
    }

    // num: 128 tasks, each 4 qi x 4 d (float4)
    if (tid < 128) {
        int qi0 = (tid >> 4) * 4;
        int d0  = (tid & 15) * 4;
        float4 acc[4];
        #pragma unroll
        for (int r = 0; r < 4; r++) acc[r] = make_float4(0.f, 0.f, 0.f, 0.f);
        #pragma unroll 4
        for (int p = 0; p < 96; p++) {
            float4 vv = *(const float4*)&sv[p * SVS + d0];
            #pragma unroll
            for (int r = 0; r < 4; r++) {
                float w = sw[(qi0 + r) * SWS + p];
                acc[r].x += w * vv.x; acc[r].y += w * vv.y;
                acc[r].z += w * vv.z; acc[r].w += w * vv.w;
            }
        }
        #pragma unroll
        for (int r = 0; r < 4; r++)
            *(float4*)(numL + ((size_t)b * nl + blk * CB + qi0 + r) * D_ + h * DH_ + d0) = acc[r];
    }
}

// ---------------- combine ----------------
__global__ void combine(const float* __restrict__ num, const float* __restrict__ den,
                        const int* __restrict__ qmask, float* __restrict__ att)
{
    int i = blockIdx.x * blockDim.x + threadIdx.x;
    if (i >= B_ * N0_ * D_) return;
    int dh = i & 63;
    int h  = (i >> 6) & 15;
    int n  = (i >> 10) & (N0_ - 1);
    int b  = i >> 23;
    float ns = 0.f, ds = 0.f;
    size_t toff = 0;
    #pragma unroll
    for (int l = 0; l < LVLS; l++) {
        int nl = N0_ >> l;
        size_t tk = toff + (size_t)b * nl + (n >> l);
        ns += num[tk * D_ + h * DH_ + dh];
        ds += den[tk * H_ + h];
        toff += (size_t)B_ * nl;
    }
    att[i] = ns / (ds + 1e-9f) * (float)qmask[b * N0_ + n];
}

// ---------------- host launch ----------------
extern "C" void kernel_launch(void* const* d_in, const int* in_sizes, int n_in,
                              void* d_out, int out_size)
{
    const float* inputs_q  = (const float*)d_in[0];
    const float* inputs_kv = (const float*)d_in[1];
    const int*   qmask     = (const int*)d_in[2];
    const int*   kmask     = (const int*)d_in[3];
    const float* Wq        = (const float*)d_in[4];
    const float* bq        = (const float*)d_in[5];
    const float* Wk        = (const float*)d_in[6];
    const float* bk        = (const float*)d_in[7];
    const float* Wv        = (const float*)d_in[8];
    const float* bv        = (const float*)d_in[9];
    const float* Wo        = (const float*)d_in[10];
    const float* bo        = (const float*)d_in[11];
    const float* rpb       = (const float*)d_in[12];
    float* out             = (float*)d_out;

    float *qp, *kp, *vp, *nump, *denp, *mp, *attp;
    cudaGetSymbolAddress((void**)&qp,   g_q);
    cudaGetSymbolAddress((void**)&kp,   g_k);
    cudaGetSymbolAddress((void**)&vp,   g_v);
    cudaGetSymbolAddress((void**)&nump, g_num);
    cudaGetSymbolAddress((void**)&denp, g_den);
    cudaGetSymbolAddress((void**)&mp,   g_m);
    cudaGetSymbolAddress((void**)&attp, g_att);

    cudaFuncSetAttribute(hier_attn, cudaFuncAttributeMaxDynamicSharedMemorySize, ATTN_SMEM);
    cudaFuncSetAttribute(gemm_f16, cudaFuncAttributeMaxDynamicSharedMemorySize, GEMM_SMEM);

    const int M = B_ * N0_;
    const float scale = 0.125f;

    // 4 idempotent warmup-ish launches so ncu (-s 5 -c 1) lands on a GEMM
    for (int r = 0; r < 4; r++)
        mask_init<<<(B_ * N0_ + 255) / 256, 256>>>(kmask, mp, B_ * N0_);

    dim3 gemmGrid(D_ / 128, M / 128);
    gemm_f16<<<gemmGrid, 256, GEMM_SMEM>>>(inputs_q,  Wq, qp, M, D_, D_, scale, bq, nullptr);
    gemm_f16<<<gemmGrid, 256, GEMM_SMEM>>>(inputs_kv, Wk, kp, M, D_, D_, 1.f, bk, nullptr);
    gemm_f16<<<gemmGrid, 256, GEMM_SMEM>>>(inputs_kv, Wv, vp, M, D_, D_, 1.f, bv, kmask);

    size_t toff = 0;
    int nl = N0_;
    for (int l = 0; l < LVLS; l++) {
        dim3 ag(nl / CB, H_, B_);
        hier_attn<<<ag, 256, ATTN_SMEM>>>(
            qp + toff * D_, kp + toff * D_, vp + toff * D_, mp + toff,
            rpb + (size_t)l * H_ * (4 * CB - 1),
            nump + toff * D_, denp + toff * H_, nl, l);
        if (l < LVLS - 1) {
            int nl2 = nl / 2;
            size_t toff2 = toff + (size_t)B_ * nl;
            int tot = B_ * nl2 * D_;
            coarsen<<<(tot + 255) / 256, 256>>>(qp + toff * D_, qp + toff2 * D_, nl2, D_);
            coarsen<<<(tot + 255) / 256, 256>>>(kp + toff * D_, kp + toff2 * D_, nl2, D_);
            coarsen<<<(tot + 255) / 256, 256>>>(vp + toff * D_, vp + toff2 * D_, nl2, D_);
            int totm = B_ * nl2;
            coarsen<<<(totm + 255) / 256, 256>>>(mp + toff, mp + toff2, nl2, 1);
        }
        toff += (size_t)B_ * nl;
        nl >>= 1;
    }

    int totc = B_ * N0_ * D_;
    combine<<<(totc + 255) / 256, 256>>>(nump, denp, qmask, attp);

    gemm_f16<<<gemmGrid, 256, GEMM_SMEM>>>(attp, Wo, out, M, D_, D_, 1.f, bo, nullptr);
}